// round 2
// baseline (speedup 1.0000x reference)
#include <cuda_runtime.h>

typedef unsigned long long u64;

#define B_  512
#define T_  512
#define F_  13
#define H_  128
#define O1_ 64

// 134MB scratch for hidden states: hs[(b*T + t)*H + j]
__device__ float g_hs[(size_t)B_ * T_ * H_];

__device__ __forceinline__ u64 fma2(u64 a, u64 b, u64 c) {
    u64 d;
    asm("fma.rn.f32x2 %0, %1, %2, %3;" : "=l"(d) : "l"(a), "l"(b), "l"(c));
    return d;
}
__device__ __forceinline__ float f2sum(u64 a) {
    float lo, hi;
    asm("mov.b64 {%0, %1}, %2;" : "=f"(lo), "=f"(hi) : "l"(a));
    return lo + hi;
}
__device__ __forceinline__ u64 pack2(float lo, float hi) {
    u64 r;
    asm("mov.b64 %0, {%1, %2};" : "=l"(r) : "f"(lo), "f"(hi));
    return r;
}
// tanh(x) = 1 - 2/(1+e^{2x}); abs err ~1e-7, inf-safe at both ends.
__device__ __forceinline__ float tanh_fast(float x) {
    float e = __expf(2.f * x);
    return 1.f - __fdividef(2.f, 1.f + e);
}

// ---------------------------------------------------------------------------
// Kernel 1: persistent recurrent scan.
// 128 CTAs x 128 threads; CTA c owns batch rows 4c..4c+3.
// Thread j keeps W_hh[j][:] (64 x u64) and W_ih[j][:] in registers.
// h lives in smem; per step: inproj + h@W_hh^T + tanh, write h to g_hs.
// ---------------------------------------------------------------------------
__global__ void __launch_bounds__(128, 1) rnn_scan(
    const float* __restrict__ x,
    const float* __restrict__ W_ih,
    const float* __restrict__ W_hh,
    const float* __restrict__ b_ih,
    const float* __restrict__ b_hh)
{
    __shared__ __align__(16) float Hs[4 * H_];   // h[r][j]
    __shared__ __align__(16) float Xs[4 * 16];   // x row, padded 13->16

    const int tid  = threadIdx.x;
    const int j    = tid;
    const int row0 = blockIdx.x * 4;

    // W_hh row j into 64 u64 registers (pairs of consecutive k)
    u64 w[64];
    {
        const ulonglong2* wrow = (const ulonglong2*)(W_hh + (size_t)j * H_);
#pragma unroll
        for (int m = 0; m < 32; m++) {
            ulonglong2 v = wrow[m];
            w[2 * m]     = v.x;
            w[2 * m + 1] = v.y;
        }
    }

    // W_ih row j, padded to 16 floats, packed to 8 u64
    u64 wihp[8];
    {
        float wih[16];
#pragma unroll
        for (int f = 0; f < 16; f++)
            wih[f] = (f < F_) ? W_ih[j * F_ + f] : 0.f;
#pragma unroll
        for (int q = 0; q < 8; q++)
            wihp[q] = pack2(wih[2 * q], wih[2 * q + 1]);
    }

    const float bsum = b_ih[j] + b_hh[j];

    // init shared state
#pragma unroll
    for (int r = 0; r < 4; r++) Hs[r * H_ + j] = 0.f;
    if (tid < 64) Xs[tid] = 0.f;
    __syncthreads();

    // loader threads: tid < 52 cover (r = tid/13, f = tid%13)
    const int pr = tid / 13;
    const int pf = tid - pr * 13;
    const bool is_loader = (tid < 52);
    if (is_loader)
        Xs[pr * 16 + pf] = x[((size_t)(row0 + pr) * T_ + 0) * F_ + pf];
    __syncthreads();

    // per-row output pointers into g_hs (stride H_ per step)
    float* hp0 = g_hs + ((size_t)(row0 + 0) * T_) * H_ + j;
    float* hp1 = g_hs + ((size_t)(row0 + 1) * T_) * H_ + j;
    float* hp2 = g_hs + ((size_t)(row0 + 2) * T_) * H_ + j;
    float* hp3 = g_hs + ((size_t)(row0 + 3) * T_) * H_ + j;

    const float* xptr = x + ((size_t)(row0 + pr) * T_) * F_ + pf;

    for (int t = 0; t < T_; t++) {
        // prefetch x(t+1) early (consumed after the barrier)
        float xn = 0.f;
        if (is_loader) {
            int tn = (t + 1 < T_) ? (t + 1) : t;
            xn = __ldg(xptr + (size_t)tn * F_);
        }

        u64 acc0[4], acc1[4];
#pragma unroll
        for (int r = 0; r < 4; r++) { acc0[r] = 0ull; acc1[r] = 0ull; }

        // input projection: 16 padded x values per row
#pragma unroll
        for (int r = 0; r < 4; r++) {
            const ulonglong2* xr = (const ulonglong2*)(Xs + r * 16);
            ulonglong2 xa = xr[0], xb = xr[1], xc = xr[2], xd = xr[3];
            acc0[r] = fma2(xa.x, wihp[0], acc0[r]);
            acc1[r] = fma2(xa.y, wihp[1], acc1[r]);
            acc0[r] = fma2(xb.x, wihp[2], acc0[r]);
            acc1[r] = fma2(xb.y, wihp[3], acc1[r]);
            acc0[r] = fma2(xc.x, wihp[4], acc0[r]);
            acc1[r] = fma2(xc.y, wihp[5], acc1[r]);
            acc0[r] = fma2(xd.x, wihp[6], acc0[r]);
            acc1[r] = fma2(xd.y, wihp[7], acc1[r]);
        }

        // recurrence: h(t) @ W_hh[j][:]
#pragma unroll
        for (int m = 0; m < 32; m++) {
            ulonglong2 h0 = *(const ulonglong2*)(Hs + 0 * H_ + 4 * m);
            ulonglong2 h1 = *(const ulonglong2*)(Hs + 1 * H_ + 4 * m);
            ulonglong2 h2 = *(const ulonglong2*)(Hs + 2 * H_ + 4 * m);
            ulonglong2 h3 = *(const ulonglong2*)(Hs + 3 * H_ + 4 * m);
            acc0[0] = fma2(h0.x, w[2 * m], acc0[0]);
            acc0[1] = fma2(h1.x, w[2 * m], acc0[1]);
            acc0[2] = fma2(h2.x, w[2 * m], acc0[2]);
            acc0[3] = fma2(h3.x, w[2 * m], acc0[3]);
            acc1[0] = fma2(h0.y, w[2 * m + 1], acc1[0]);
            acc1[1] = fma2(h1.y, w[2 * m + 1], acc1[1]);
            acc1[2] = fma2(h2.y, w[2 * m + 1], acc1[2]);
            acc1[3] = fma2(h3.y, w[2 * m + 1], acc1[3]);
        }

        float hn[4];
#pragma unroll
        for (int r = 0; r < 4; r++) {
            float pre = bsum + f2sum(acc0[r]) + f2sum(acc1[r]);
            hn[r] = tanh_fast(pre);
        }

        // write h(t+1) to global scratch (coalesced, independent of smem sync)
        *hp0 = hn[0]; hp0 += H_;
        *hp1 = hn[1]; hp1 += H_;
        *hp2 = hn[2]; hp2 += H_;
        *hp3 = hn[3]; hp3 += H_;

        __syncthreads();   // all reads of Hs/Xs for step t done
#pragma unroll
        for (int r = 0; r < 4; r++) Hs[r * H_ + j] = hn[r];
        if (is_loader) Xs[pr * 16 + pf] = xn;
        __syncthreads();   // new Hs/Xs visible
    }
}

// ---------------------------------------------------------------------------
// Kernel 2: fused fc1(relu) + fc2(sigmoid) over all (b,t) rows.
// Block = 256 threads handles 128 rows x 64 outputs.
// warp og owns 8 fc1-outputs; lane ro owns rows {ro, ro+32, ro+64, ro+96}.
// w loads are warp-broadcast; h tile padded to 132 floats/row -> conflict-free.
// ---------------------------------------------------------------------------
__global__ void __launch_bounds__(256, 1) rnn_fc(
    const float* __restrict__ fc1_w,
    const float* __restrict__ fc1_b,
    const float* __restrict__ fc2_w,
    const float* __restrict__ fc2_b,
    float* __restrict__ out)
{
    extern __shared__ __align__(16) char smem2[];
    float* Ws  = (float*)smem2;                  // [64][128]   32KB
    float* Hsh = Ws + O1_ * H_;                  // [128][132]  67.6KB
    float* red = Hsh + 128 * 132;                // [128][8]    4KB

    const int tid = threadIdx.x;
    const size_t rowbase = (size_t)blockIdx.x * 128;

    // stage fc1 weights
    for (int i = tid; i < (O1_ * H_) / 4; i += 256)
        ((float4*)Ws)[i] = ((const float4*)fc1_w)[i];

    // stage 128-row h tile (padded rows)
    for (int i = tid; i < 128 * 32; i += 256) {
        int row = i >> 5, m = i & 31;
        float4 v = ((const float4*)g_hs)[(rowbase + row) * 32 + m];
        *(float4*)(Hsh + row * 132 + 4 * m) = v;
    }
    __syncthreads();

    const int ro = tid & 31;     // lane -> row subgroup
    const int og = tid >> 5;     // warp -> 8 consecutive fc1 outputs

    u64 acc[4][8];
#pragma unroll
    for (int s = 0; s < 4; s++)
#pragma unroll
        for (int p = 0; p < 8; p++) acc[s][p] = 0ull;

#pragma unroll 4
    for (int k4 = 0; k4 < 32; k4++) {
        ulonglong2 hv[4];
#pragma unroll
        for (int s = 0; s < 4; s++)
            hv[s] = *(const ulonglong2*)(Hsh + (ro + 32 * s) * 132 + 4 * k4);
        ulonglong2 wv[8];
#pragma unroll
        for (int p = 0; p < 8; p++)
            wv[p] = *(const ulonglong2*)(Ws + (og * 8 + p) * H_ + 4 * k4);
#pragma unroll
        for (int p = 0; p < 8; p++)
#pragma unroll
            for (int s = 0; s < 4; s++)
                acc[s][p] = fma2(hv[s].x, wv[p].x, acc[s][p]);
#pragma unroll
        for (int p = 0; p < 8; p++)
#pragma unroll
            for (int s = 0; s < 4; s++)
                acc[s][p] = fma2(hv[s].y, wv[p].y, acc[s][p]);
    }

    // relu(fc1) and partial fc2 dot
    float part[4] = {0.f, 0.f, 0.f, 0.f};
#pragma unroll
    for (int p = 0; p < 8; p++) {
        int o    = og * 8 + p;
        float b1 = __ldg(fc1_b + o);
        float w2 = __ldg(fc2_w + o);
#pragma unroll
        for (int s = 0; s < 4; s++) {
            float y = f2sum(acc[s][p]) + b1;
            y = fmaxf(y, 0.f);
            part[s] = fmaf(y, w2, part[s]);
        }
    }
#pragma unroll
    for (int s = 0; s < 4; s++)
        red[(ro + 32 * s) * 8 + og] = part[s];
    __syncthreads();

    if (tid < 128) {
        float sum = __ldg(fc2_b);
#pragma unroll
        for (int q = 0; q < 8; q++) sum += red[tid * 8 + q];
        out[rowbase + tid] = __fdividef(1.f, 1.f + __expf(-sum));
    }
}

// ---------------------------------------------------------------------------

extern "C" void kernel_launch(void* const* d_in, const int* in_sizes, int n_in,
                              void* d_out, int out_size)
{
    const float* x     = (const float*)d_in[0];
    const float* W_ih  = (const float*)d_in[1];
    const float* W_hh  = (const float*)d_in[2];
    const float* b_ih  = (const float*)d_in[3];
    const float* b_hh  = (const float*)d_in[4];
    const float* fc1_w = (const float*)d_in[5];
    const float* fc1_b = (const float*)d_in[6];
    const float* fc2_w = (const float*)d_in[7];
    const float* fc2_b = (const float*)d_in[8];
    float* out = (float*)d_out;

    const int fc_smem = (O1_ * H_ + 128 * 132 + 128 * 8) * sizeof(float); // 104448
    cudaFuncSetAttribute(rnn_fc, cudaFuncAttributeMaxDynamicSharedMemorySize, fc_smem);

    rnn_scan<<<128, 128>>>(x, W_ih, W_hh, b_ih, b_hh);
    rnn_fc<<<(B_ * T_) / 128, 256, fc_smem>>>(fc1_w, fc1_b, fc2_w, fc2_b, out);
}

// round 3
// speedup vs baseline: 1.3213x; 1.3213x over previous
#include <cuda_runtime.h>

typedef unsigned long long u64;

#define B_  512
#define T_  512
#define F_  13
#define H_  128
#define O1_ 64

__device__ __forceinline__ u64 fma2(u64 a, u64 b, u64 c) {
    u64 d;
    asm("fma.rn.f32x2 %0, %1, %2, %3;" : "=l"(d) : "l"(a), "l"(b), "l"(c));
    return d;
}
__device__ __forceinline__ float f2sum(u64 a) {
    float lo, hi;
    asm("mov.b64 {%0, %1}, %2;" : "=f"(lo), "=f"(hi) : "l"(a));
    return lo + hi;
}
__device__ __forceinline__ u64 pack2(float lo, float hi) {
    u64 r;
    asm("mov.b64 %0, {%1, %2};" : "=l"(r) : "f"(lo), "f"(hi));
    return r;
}
// tanh(x) = 1 - 2/(1+e^{2x}); abs err ~1e-7, inf-safe.
__device__ __forceinline__ float tanh_fast(float x) {
    float e = __expf(2.f * x);
    return 1.f - __fdividef(2.f, 1.f + e);
}
__device__ __forceinline__ void barsync() {
    asm volatile("bar.sync 0;" ::: "memory");
}

// ---------------------------------------------------------------------------
// Fused persistent RNN: scan + fc1(relu) + fc2(sigmoid), one kernel.
// 128 CTAs x 256 threads. CTA c owns batch rows 4c..4c+3.
//   threads   0..127 (warps 0-3): recurrence. Thread j holds W_hh[j][:] in regs.
//   threads 128..255 (warps 4-7): fc. Thread (o = ft&63, rp = ft>>6) holds
//       fc1_w[o][:] in regs, processes rows {2rp, 2rp+1}, one step behind.
// Shared: Hs[4][128] hidden state, Xs[4][16] current x, red[8] fc partials.
// Both halves execute T_+1 iterations with exactly two bar.sync each, so the
// counting barriers pair up across the divergent specialization.
// ---------------------------------------------------------------------------
__global__ void __launch_bounds__(256, 1) rnn_fused(
    const float* __restrict__ x,
    const float* __restrict__ W_ih,
    const float* __restrict__ W_hh,
    const float* __restrict__ b_ih,
    const float* __restrict__ b_hh,
    const float* __restrict__ fc1_w,
    const float* __restrict__ fc1_b,
    const float* __restrict__ fc2_w,
    const float* __restrict__ fc2_b,
    float* __restrict__ out)
{
    __shared__ __align__(16) float Hs[4 * H_];
    __shared__ __align__(16) float Xs[4 * 16];
    __shared__ float red[8];

    const int tid  = threadIdx.x;
    const int row0 = blockIdx.x * 4;

    // ---- convergent init ----
    if (tid < H_) {
#pragma unroll
        for (int r = 0; r < 4; r++) Hs[r * H_ + tid] = 0.f;
    }
    if (tid < 64) Xs[tid] = 0.f;
    __syncthreads();
    {
        // loaders live in the fc half: ft in [0,52)
        int ft = tid - 128;
        if (ft >= 0 && ft < 52) {
            int pr = ft / 13, pf = ft - pr * 13;
            Xs[pr * 16 + pf] = x[((size_t)(row0 + pr) * T_) * F_ + pf];
        }
    }
    __syncthreads();

    if (tid < 128) {
        // =================== RECURRENCE HALF ===================
        const int j = tid;

        u64 w[64];
        {
            const ulonglong2* wrow = (const ulonglong2*)(W_hh + (size_t)j * H_);
#pragma unroll
            for (int m = 0; m < 32; m++) {
                ulonglong2 v = wrow[m];
                w[2 * m] = v.x; w[2 * m + 1] = v.y;
            }
        }
        u64 wihp[8];
        {
            float wih[16];
#pragma unroll
            for (int f = 0; f < 16; f++)
                wih[f] = (f < F_) ? __ldg(W_ih + j * F_ + f) : 0.f;
#pragma unroll
            for (int q = 0; q < 8; q++)
                wihp[q] = pack2(wih[2 * q], wih[2 * q + 1]);
        }
        const float bsum = __ldg(b_ih + j) + __ldg(b_hh + j);

        for (int t = 0; t <= T_; t++) {
            float hn[4];
            if (t < T_) {
                u64 acc0[4], acc1[4];
#pragma unroll
                for (int r = 0; r < 4; r++) { acc0[r] = 0ull; acc1[r] = 0ull; }

                // input projection from Xs (padded 13->16)
#pragma unroll
                for (int r = 0; r < 4; r++) {
                    const ulonglong2* xr = (const ulonglong2*)(Xs + r * 16);
                    ulonglong2 xa = xr[0], xb = xr[1], xc = xr[2], xd = xr[3];
                    acc0[r] = fma2(xa.x, wihp[0], acc0[r]);
                    acc1[r] = fma2(xa.y, wihp[1], acc1[r]);
                    acc0[r] = fma2(xb.x, wihp[2], acc0[r]);
                    acc1[r] = fma2(xb.y, wihp[3], acc1[r]);
                    acc0[r] = fma2(xc.x, wihp[4], acc0[r]);
                    acc1[r] = fma2(xc.y, wihp[5], acc1[r]);
                    acc0[r] = fma2(xd.x, wihp[6], acc0[r]);
                    acc1[r] = fma2(xd.y, wihp[7], acc1[r]);
                }
                // recurrence h(t) @ W_hh[j][:]  (Hs reads are warp-uniform broadcasts)
#pragma unroll
                for (int m = 0; m < 32; m++) {
                    ulonglong2 h0 = *(const ulonglong2*)(Hs + 0 * H_ + 4 * m);
                    ulonglong2 h1 = *(const ulonglong2*)(Hs + 1 * H_ + 4 * m);
                    ulonglong2 h2 = *(const ulonglong2*)(Hs + 2 * H_ + 4 * m);
                    ulonglong2 h3 = *(const ulonglong2*)(Hs + 3 * H_ + 4 * m);
                    acc0[0] = fma2(h0.x, w[2 * m], acc0[0]);
                    acc0[1] = fma2(h1.x, w[2 * m], acc0[1]);
                    acc0[2] = fma2(h2.x, w[2 * m], acc0[2]);
                    acc0[3] = fma2(h3.x, w[2 * m], acc0[3]);
                    acc1[0] = fma2(h0.y, w[2 * m + 1], acc1[0]);
                    acc1[1] = fma2(h1.y, w[2 * m + 1], acc1[1]);
                    acc1[2] = fma2(h2.y, w[2 * m + 1], acc1[2]);
                    acc1[3] = fma2(h3.y, w[2 * m + 1], acc1[3]);
                }
#pragma unroll
                for (int r = 0; r < 4; r++)
                    hn[r] = tanh_fast(bsum + f2sum(acc0[r]) + f2sum(acc1[r]));
            }
            barsync();   // B: all reads of Hs/Xs for this step done
            if (t < T_) {
#pragma unroll
                for (int r = 0; r < 4; r++) Hs[r * H_ + j] = hn[r];
            }
            barsync();   // A: new Hs/Xs visible
        }
    } else {
        // =================== FC HALF ===================
        const int ft = tid - 128;
        const int o  = ft & 63;          // fc1 output index
        const int rp = ft >> 6;          // row pair: rows {2rp, 2rp+1}
        const int wloc = ft >> 5;        // 0..3: local warp id
        const int lane = ft & 31;

        u64 fw[64];
        {
            const ulonglong2* fr = (const ulonglong2*)(fc1_w + (size_t)o * H_);
#pragma unroll
            for (int m = 0; m < 32; m++) {
                ulonglong2 v = fr[m];
                fw[2 * m] = v.x; fw[2 * m + 1] = v.y;
            }
        }
        const float b1 = __ldg(fc1_b + o);
        const float w2 = __ldg(fc2_w + o);
        const float b2 = __ldg(fc2_b);

        const bool is_loader = (ft < 52);
        const int  pr = ft / 13, pf = ft - pr * 13;
        const float* xptr = x + ((size_t)(row0 + pr) * T_) * F_ + pf;

        const float* h0p = Hs + (2 * rp) * H_;
        const float* h1p = Hs + (2 * rp + 1) * H_;

        for (int t = 0; t <= T_; t++) {
            // prefetch x(t+1) for the recurrence (consumed after bar B)
            float xn = 0.f;
            if (is_loader && t < T_) {
                int tn = (t + 1 < T_) ? (t + 1) : t;
                xn = __ldg(xptr + (size_t)tn * F_);
            }

            float part0 = 0.f, part1 = 0.f;
            if (t > 0) {
                // Hs currently holds h output of step t-1
                u64 a0 = 0ull, a1 = 0ull, c0 = 0ull, c1 = 0ull;
#pragma unroll
                for (int m = 0; m < 32; m++) {
                    ulonglong2 hv0 = *(const ulonglong2*)(h0p + 4 * m);
                    ulonglong2 hv1 = *(const ulonglong2*)(h1p + 4 * m);
                    a0 = fma2(hv0.x, fw[2 * m],     a0);
                    a1 = fma2(hv0.y, fw[2 * m + 1], a1);
                    c0 = fma2(hv1.x, fw[2 * m],     c0);
                    c1 = fma2(hv1.y, fw[2 * m + 1], c1);
                }
                float y0 = fmaxf(f2sum(a0) + f2sum(a1) + b1, 0.f);
                float y1 = fmaxf(f2sum(c0) + f2sum(c1) + b1, 0.f);
                part0 = y0 * w2;
                part1 = y1 * w2;
#pragma unroll
                for (int off = 16; off > 0; off >>= 1) {
                    part0 += __shfl_xor_sync(0xffffffffu, part0, off);
                    part1 += __shfl_xor_sync(0xffffffffu, part1, off);
                }
                if (lane == 0) {
                    red[wloc * 2 + 0] = part0;
                    red[wloc * 2 + 1] = part1;
                }
            }
            barsync();   // B
            if (is_loader && t < T_) Xs[pr * 16 + pf] = xn;
            if (t > 0 && ft < 4) {
                // row r = ft: combine the two warp-halves, sigmoid, store
                int r = ft;
                int i1 = (r >> 1) * 4 + (r & 1);
                float s = red[i1] + red[i1 + 2] + b2;
                out[(size_t)(row0 + r) * T_ + (t - 1)] =
                    __fdividef(1.f, 1.f + __expf(-s));
            }
            barsync();   // A
        }
    }
}

// ---------------------------------------------------------------------------

extern "C" void kernel_launch(void* const* d_in, const int* in_sizes, int n_in,
                              void* d_out, int out_size)
{
    const float* x     = (const float*)d_in[0];
    const float* W_ih  = (const float*)d_in[1];
    const float* W_hh  = (const float*)d_in[2];
    const float* b_ih  = (const float*)d_in[3];
    const float* b_hh  = (const float*)d_in[4];
    const float* fc1_w = (const float*)d_in[5];
    const float* fc1_b = (const float*)d_in[6];
    const float* fc2_w = (const float*)d_in[7];
    const float* fc2_b = (const float*)d_in[8];
    float* out = (float*)d_out;

    rnn_fused<<<128, 256>>>(x, W_ih, W_hh, b_ih, b_hh,
                            fc1_w, fc1_b, fc2_w, fc2_b, out);
}